// round 2
// baseline (speedup 1.0000x reference)
#include <cuda_runtime.h>

#define S_LEN 512
#define B_SZ 512
#define T_TAGS 64
#define START_TAG 62
#define STOP_TAG 63
#define KH 32                 // K-elements per thread (split-K = 2)

__device__ float g_res[B_SZ];
__device__ unsigned g_ticket = 0;   // wraps every 512 increments (graph-replay safe)

__global__ __launch_bounds__(128)
void crf_forward_kernel(const float* __restrict__ feats,
                        const int* __restrict__ tags,
                        const float* __restrict__ mask,
                        const float* __restrict__ trans,
                        float* __restrict__ out)
{
    const int b = blockIdx.x;
    const int t = threadIdx.x;            // 0..127
    const int j = t >> 1;                 // tag 0..63
    const int g = t & 1;                  // K-half
    const int warp = t >> 5, lane = t & 31;

    __shared__ __align__(16) float A[2][T_TAGS];   // double-buffered alpha
    __shared__ float smax[4];
    __shared__ float ssum[4];
    __shared__ float sred[4][2];
    __shared__ unsigned s_last;

    // ---- E half-column (exp of transitions) in registers ----
    float Ecol[KH];
    float wsum = 0.0f;
    const int ibase = g * KH;
#pragma unroll
    for (int i = 0; i < KH; i++) {
        Ecol[i] = __expf(__ldg(&trans[(ibase + i) * T_TAGS + j]));  // exp(-1e4) -> 0
        wsum += Ecol[i];
    }
    wsum += __shfl_xor_sync(0xffffffffu, wsum, 1);
    const float w = 1.0f + wsum;                     // step-1 analytic weight
    const float Estop = __expf(__ldg(&trans[STOP_TAG * T_TAGS + j]));

    // ---- gold score: parallel over s ----
    float sc = 0.0f, msum = 0.0f;
#pragma unroll
    for (int s = t; s < S_LEN; s += 128) {
        int   tg = __ldg(&tags[s * B_SZ + b]);
        int   pv = (s == 0) ? START_TAG : __ldg(&tags[(s - 1) * B_SZ + b]);
        float m  = __ldg(&mask[s * B_SZ + b]);
        float e  = __ldg(&feats[(s * B_SZ + b) * T_TAGS + tg]);
        sc   += (e + __ldg(&trans[pv * T_TAGS + tg])) * m;
        msum += m;
    }
#pragma unroll
    for (int off = 16; off; off >>= 1) {
        sc   += __shfl_xor_sync(0xffffffffu, sc, off);
        msum += __shfl_xor_sync(0xffffffffu, msum, off);
    }
    if (lane == 0) { sred[warp][0] = sc; sred[warp][1] = msum; }
    __syncthreads();
    float score_total = 0.0f;
    if (t == 0) {
        float st = sred[0][0] + sred[1][0] + sred[2][0] + sred[3][0];
        float mt = sred[0][1] + sred[1][1] + sred[2][1] + sred[3][1];
        int   li = (int)(mt + 0.5f) - 1;
        int   lt = __ldg(&tags[li * B_SZ + b]);
        score_total = st + __ldg(&trans[lt * T_TAGS + STOP_TAG]);
    }
    __syncthreads();

    // ---- forward recursion: linear domain, virtual rescaling ----
    // true log_alpha[j] = log(A[cur][j]) + C - 10000
    float C = 0.0f;
    float lmx = 0.0f;          // pending scale (log of max), 0 on non-rescale steps
    float val = 0.0f;
    bool  started = false;
    int   cur = 0;

    float m_cur = __ldg(&mask[b]);
    float f_cur = __ldg(&feats[b * T_TAGS + j]);

    for (int s = 0; s < S_LEN; s++) {
        float m_nxt = 0.0f, f_nxt = 0.0f;
        if (s + 1 < S_LEN) {
            m_nxt = __ldg(&mask[(s + 1) * B_SZ + b]);
            f_nxt = __ldg(&feats[((s + 1) * B_SZ + b) * T_TAGS + j]);
        }
        if (m_cur > 0.0f) {                          // uniform across block
            if (started) {
                // exp does NOT depend on the matvec -> compute first, off the chain
                float ef = __expf(f_cur - lmx);
                const float4* a4 = (const float4*)(A[cur] + ibase);
                float acc0 = 0.f, acc1 = 0.f, acc2 = 0.f, acc3 = 0.f;
#pragma unroll
                for (int i4 = 0; i4 < KH / 4; i4++) {   // 8 LDS.128, 32 FMA
                    float4 a = a4[i4];
                    acc0 = fmaf(a.x, Ecol[4 * i4 + 0], acc0);
                    acc1 = fmaf(a.y, Ecol[4 * i4 + 1], acc1);
                    acc2 = fmaf(a.z, Ecol[4 * i4 + 2], acc2);
                    acc3 = fmaf(a.w, Ecol[4 * i4 + 3], acc3);
                }
                float acc = (acc0 + acc1) + (acc2 + acc3);
                acc += __shfl_xor_sync(0xffffffffu, acc, 1);  // combine K-halves
                C += lmx;
                val = acc * ef;
            } else {
                val = __expf(f_cur) * w;             // analytic first step
                started = true;
            }
            int nxt = cur ^ 1;
            if (g == 0) A[nxt][j] = val;

            bool rescale = ((s & 3) == 3);
            if (rescale) {
                float v = val;
#pragma unroll
                for (int off = 16; off; off >>= 1)
                    v = fmaxf(v, __shfl_xor_sync(0xffffffffu, v, off));
                if (lane == 0) smax[warp] = v;
            }
            __syncthreads();
            lmx = rescale
                ? __logf(fmaxf(fmaxf(smax[0], smax[1]), fmaxf(smax[2], smax[3])))
                : 0.0f;
            cur = nxt;
        }
        m_cur = m_nxt; f_cur = f_nxt;
    }

    // ---- log_z = C + log( sum_j A[j] * Estop[j] ) - 10000 ----
    float fv = started ? val : ((j == START_TAG) ? 1.0f : 0.0f);
    if (!started) C = 10000.0f;
    float p = (g == 0) ? fv * Estop : 0.0f;          // each j counted once
#pragma unroll
    for (int off = 16; off; off >>= 1)
        p += __shfl_xor_sync(0xffffffffu, p, off);
    if (lane == 0) ssum[warp] = p;
    __syncthreads();
    if (t == 0) {
        float tot  = ssum[0] + ssum[1] + ssum[2] + ssum[3];
        float logz = C + __logf(tot) - 10000.0f;
        g_res[b] = logz - score_total;
    }

    // ---- fused finalize: last CTA reduces (fixed order -> deterministic) ----
    __threadfence();
    if (t == 0) s_last = atomicInc(&g_ticket, B_SZ - 1);
    __syncthreads();
    if (s_last == B_SZ - 1) {
        __threadfence();
        const volatile float* gr = g_res;
        float v = gr[t] + gr[t + 128] + gr[t + 256] + gr[t + 384];
#pragma unroll
        for (int off = 16; off; off >>= 1)
            v += __shfl_xor_sync(0xffffffffu, v, off);
        if (lane == 0) ssum[warp] = v;
        __syncthreads();
        if (t == 0)
            out[0] = (ssum[0] + ssum[1] + ssum[2] + ssum[3]) * (1.0f / (float)B_SZ);
    }
}

extern "C" void kernel_launch(void* const* d_in, const int* in_sizes, int n_in,
                              void* d_out, int out_size)
{
    const float* feats = (const float*)d_in[0];
    const int*   tags  = (const int*)d_in[1];
    const float* mask  = (const float*)d_in[2];
    const float* trans = (const float*)d_in[3];
    float* out = (float*)d_out;

    crf_forward_kernel<<<B_SZ, 128>>>(feats, tags, mask, trans, out);
}

// round 3
// speedup vs baseline: 1.1454x; 1.1454x over previous
#include <cuda_runtime.h>

#define S_LEN 512
#define B_SZ 512
#define T_TAGS 64
#define START_TAG 62
#define STOP_TAG 63
#define PF 4                    // prefetch depth (power of 2)

__device__ float g_res[B_SZ];
__device__ unsigned g_ticket = 0;   // wraps every 512 -> graph-replay safe

typedef unsigned long long u64;

__device__ __forceinline__ u64 pk2(float lo, float hi) {
    u64 r; asm("mov.b64 %0, {%1, %2};" : "=l"(r) : "f"(lo), "f"(hi)); return r;
}
__device__ __forceinline__ void upk2(u64 v, float& lo, float& hi) {
    asm("mov.b64 {%0, %1}, %2;" : "=f"(lo), "=f"(hi) : "l"(v));
}
__device__ __forceinline__ u64 fma2(u64 a, u64 b, u64 c) {
    u64 d; asm("fma.rn.f32x2 %0, %1, %2, %3;" : "=l"(d) : "l"(a), "l"(b), "l"(c)); return d;
}
__device__ __forceinline__ u64 add2(u64 a, u64 b) {
    u64 d; asm("add.rn.f32x2 %0, %1, %2;" : "=l"(d) : "l"(a), "l"(b)); return d;
}

__global__ __launch_bounds__(32)
void crf_forward_kernel(const float* __restrict__ feats,
                        const int* __restrict__ tags,
                        const float* __restrict__ mask,
                        const float* __restrict__ trans,
                        float* __restrict__ out)
{
    const int b    = blockIdx.x;
    const int lane = threadIdx.x;           // 0..31
    const int j0   = lane;
    const int j1   = lane + 32;

    __shared__ __align__(16) float A[T_TAGS];   // alpha (single buffer, warp-sync)
    __shared__ float s_bcast;

    // ---------------- gold score (parallel over s) ----------------
    float sc = 0.0f, msum = 0.0f;
    for (int s = lane; s < S_LEN; s += 32) {
        int   tg = __ldg(&tags[s * B_SZ + b]);
        int   pv = (s == 0) ? START_TAG : __ldg(&tags[(s - 1) * B_SZ + b]);
        float m  = __ldg(&mask[s * B_SZ + b]);
        float e  = __ldg(&feats[((size_t)s * B_SZ + b) * T_TAGS + tg]);
        sc   += (e + __ldg(&trans[pv * T_TAGS + tg])) * m;
        msum += m;
    }
#pragma unroll
    for (int off = 16; off; off >>= 1) {
        sc   += __shfl_xor_sync(0xffffffffu, sc, off);
        msum += __shfl_xor_sync(0xffffffffu, msum, off);
    }
    float score_total = 0.0f;
    if (lane == 0) {
        int li = (int)(msum + 0.5f) - 1;
        int lt = __ldg(&tags[li * B_SZ + b]);
        score_total = sc + __ldg(&trans[lt * T_TAGS + STOP_TAG]);
    }

    // ---------------- E columns, packed as f32x2 pairs ----------------
    // E0p[i] = {exp(trans[2i][j0]), exp(trans[2i+1][j0])}, same for j1.
    u64 E0p[T_TAGS / 2], E1p[T_TAGS / 2];
    float w0 = 1.0f, w1 = 1.0f;              // 1 + sum_i E[i][j]  (step-1 analytic)
#pragma unroll
    for (int i = 0; i < T_TAGS / 2; i++) {
        float a0 = __expf(__ldg(&trans[(2 * i)     * T_TAGS + j0]));
        float a1 = __expf(__ldg(&trans[(2 * i + 1) * T_TAGS + j0]));
        float b0 = __expf(__ldg(&trans[(2 * i)     * T_TAGS + j1]));
        float b1 = __expf(__ldg(&trans[(2 * i + 1) * T_TAGS + j1]));
        E0p[i] = pk2(a0, a1);  w0 += a0 + a1;
        E1p[i] = pk2(b0, b1);  w1 += b0 + b1;
    }
    const float Es0 = __expf(__ldg(&trans[STOP_TAG * T_TAGS + j0]));
    const float Es1 = __expf(__ldg(&trans[STOP_TAG * T_TAGS + j1]));

    // ---------------- prefetch pipeline (depth PF) ----------------
    float fp0[PF], fp1[PF], mp[PF];
#pragma unroll
    for (int k = 0; k < PF; k++) {
        mp[k]  = __ldg(&mask[k * B_SZ + b]);
        fp0[k] = __ldg(&feats[((size_t)k * B_SZ + b) * T_TAGS + j0]);
        fp1[k] = __ldg(&feats[((size_t)k * B_SZ + b) * T_TAGS + j1]);
    }
    const float* fptr = feats + ((size_t)PF * B_SZ + b) * T_TAGS;
    const float* mptr = mask + PF * B_SZ + b;

    // ---------------- forward recursion ----------------
    // true log_alpha[j] = log(A[j]) + C - 10000
    float C = 0.0f, lmx = 0.0f;
    float val0 = 0.0f, val1 = 0.0f;
    bool started = false;

    for (int s = 0; s < S_LEN; s++) {
        const int k = s & (PF - 1);
        float m_cur = mp[k], f0 = fp0[k], f1 = fp1[k];
        if (s + PF < S_LEN) {                           // refill, 4 steps ahead
            mp[k]  = __ldg(mptr);
            fp0[k] = __ldg(fptr + j0);
            fp1[k] = __ldg(fptr + j1);
            mptr += B_SZ;
            fptr += (size_t)B_SZ * T_TAGS;
        }
        if (m_cur > 0.0f) {                             // warp-uniform
            if (started) {
                float ef0 = __expf(f0 - lmx);           // off the matvec chain
                float ef1 = __expf(f1 - lmx);
                const ulonglong2* AU = (const ulonglong2*)A;   // broadcast LDS.128
                u64 a0a = 0, a0b = 0, a1a = 0, a1b = 0;
#pragma unroll
                for (int q = 0; q < T_TAGS / 4; q++) {  // 16 LDS.128, 64 FFMA2
                    ulonglong2 a = AU[q];
                    a0a = fma2(a.x, E0p[2 * q],     a0a);
                    a0b = fma2(a.y, E0p[2 * q + 1], a0b);
                    a1a = fma2(a.x, E1p[2 * q],     a1a);
                    a1b = fma2(a.y, E1p[2 * q + 1], a1b);
                }
                float x0, x1, y0, y1;
                u64 t0 = add2(a0a, a0b), t1 = add2(a1a, a1b);
                upk2(t0, x0, x1);  upk2(t1, y0, y1);
                C += lmx;
                val0 = (x0 + x1) * ef0;
                val1 = (y0 + y1) * ef1;
            } else {
                val0 = __expf(f0) * w0;                 // analytic first step
                val1 = __expf(f1) * w1;
                started = true;
            }
            A[j0] = val0;
            A[j1] = val1;
            if ((s & 3) == 3) {                         // rescale every 4 steps
                float v = fmaxf(val0, val1);
#pragma unroll
                for (int off = 16; off; off >>= 1)
                    v = fmaxf(v, __shfl_xor_sync(0xffffffffu, v, off));
                lmx = __logf(v);
            } else {
                lmx = 0.0f;
            }
        }
        __syncwarp();                                   // order STS -> next LDS
    }

    // ---------------- log_z and per-batch result ----------------
    float fv0 = started ? val0 : ((j0 == START_TAG) ? 1.0f : 0.0f);
    float fv1 = started ? val1 : ((j1 == START_TAG) ? 1.0f : 0.0f);
    if (!started) C = 10000.0f;
    float p = fv0 * Es0 + fv1 * Es1;
#pragma unroll
    for (int off = 16; off; off >>= 1)
        p += __shfl_xor_sync(0xffffffffu, p, off);
    if (lane == 0) {
        float logz = C + __logf(p) - 10000.0f;
        g_res[b] = logz - score_total;
        __threadfence();
        s_bcast = (float)atomicInc(&g_ticket, B_SZ - 1);
    }
    __syncwarp();

    // ---------------- fused finalize: last warp reduces ----------------
    if ((unsigned)s_bcast == B_SZ - 1) {
        __threadfence();
        const volatile float* gr = g_res;
        float v = 0.0f;
#pragma unroll
        for (int i = 0; i < B_SZ / 32; i++)             // fixed order: deterministic
            v += gr[lane + i * 32];
#pragma unroll
        for (int off = 16; off; off >>= 1)
            v += __shfl_xor_sync(0xffffffffu, v, off);
        if (lane == 0) out[0] = v * (1.0f / (float)B_SZ);
    }
}

extern "C" void kernel_launch(void* const* d_in, const int* in_sizes, int n_in,
                              void* d_out, int out_size)
{
    const float* feats = (const float*)d_in[0];
    const int*   tags  = (const int*)d_in[1];
    const float* mask  = (const float*)d_in[2];
    const float* trans = (const float*)d_in[3];
    float* out = (float*)d_out;

    crf_forward_kernel<<<B_SZ, 32>>>(feats, tags, mask, trans, out);
}

// round 4
// speedup vs baseline: 2.3003x; 2.0083x over previous
#include <cuda_runtime.h>

#define S_LEN 512
#define B_SZ 512
#define T_TAGS 64
#define START_TAG 62
#define STOP_TAG 63
#define NWARP 4
#define GRID_X (B_SZ / NWARP)   // 128 blocks

__device__ float g_res[B_SZ];
__device__ unsigned g_ticket = 0;   // wraps every GRID_X -> graph-replay safe

typedef unsigned long long u64;

static __device__ __forceinline__ u64 pk2(float lo, float hi) {
    u64 r; asm("mov.b64 %0, {%1, %2};" : "=l"(r) : "f"(lo), "f"(hi)); return r;
}
static __device__ __forceinline__ void upk2(u64 v, float& lo, float& hi) {
    asm("mov.b64 {%0, %1}, %2;" : "=f"(lo), "=f"(hi) : "l"(v));
}
static __device__ __forceinline__ u64 fma2(u64 a, u64 b, u64 c) {
    u64 d; asm("fma.rn.f32x2 %0, %1, %2, %3;" : "=l"(d) : "l"(a), "l"(b), "l"(c)); return d;
}
static __device__ __forceinline__ u64 add2(u64 a, u64 b) {
    u64 d; asm("add.rn.f32x2 %0, %1, %2;" : "=l"(d) : "l"(a), "l"(b)); return d;
}

__global__ __launch_bounds__(128)
void crf_forward_kernel(const float* __restrict__ feats,
                        const int* __restrict__ tags,
                        const float* __restrict__ mask,
                        const float* __restrict__ trans,
                        float* __restrict__ out)
{
    const int warp = threadIdx.x >> 5;
    const int lane = threadIdx.x & 31;
    const int b    = blockIdx.x * NWARP + warp;     // one batch per warp
    const int j0   = lane, j1 = lane + 32;

    __shared__ __align__(16) float A[NWARP][T_TAGS];  // per-warp alpha
    __shared__ float sred[NWARP];
    __shared__ unsigned s_t;

    // ---------------- gold score (per-warp, parallel over s) ----------------
    float sc = 0.0f, msum = 0.0f;
#pragma unroll 4
    for (int s = lane; s < S_LEN; s += 32) {
        int   tg = __ldg(&tags[s * B_SZ + b]);
        int   pv = (s == 0) ? START_TAG : __ldg(&tags[(s - 1) * B_SZ + b]);
        float m  = __ldg(&mask[s * B_SZ + b]);
        float e  = __ldg(&feats[((size_t)s * B_SZ + b) * T_TAGS + tg]);
        sc   += (e + __ldg(&trans[pv * T_TAGS + tg])) * m;
        msum += m;
    }
#pragma unroll
    for (int off = 16; off; off >>= 1) {
        sc   += __shfl_xor_sync(0xffffffffu, sc, off);
        msum += __shfl_xor_sync(0xffffffffu, msum, off);
    }
    float score_total = 0.0f;
    if (lane == 0) {
        int li = (int)(msum + 0.5f) - 1;
        int lt = __ldg(&tags[li * B_SZ + b]);
        score_total = sc + __ldg(&trans[lt * T_TAGS + STOP_TAG]);
    }

    // ---------------- E columns packed f32x2 ----------------
    u64 E0p[T_TAGS / 2], E1p[T_TAGS / 2];
    float w0 = 1.0f, w1 = 1.0f;                 // step-1 analytic weights
#pragma unroll
    for (int i = 0; i < T_TAGS / 2; i++) {
        float a0 = __expf(__ldg(&trans[(2 * i)     * T_TAGS + j0]));
        float a1 = __expf(__ldg(&trans[(2 * i + 1) * T_TAGS + j0]));
        float c0 = __expf(__ldg(&trans[(2 * i)     * T_TAGS + j1]));
        float c1 = __expf(__ldg(&trans[(2 * i + 1) * T_TAGS + j1]));
        E0p[i] = pk2(a0, a1);  w0 += a0 + a1;
        E1p[i] = pk2(c0, c1);  w1 += c0 + c1;
    }
    const float Es0 = __expf(__ldg(&trans[STOP_TAG * T_TAGS + j0]));
    const float Es1 = __expf(__ldg(&trans[STOP_TAG * T_TAGS + j1]));

    // ---------------- register prefetch (compile-time slots) ----------------
    float fa0, fa1, fa2, fa3, fb0, fb1, fb2, fb3, mm0, mm1, mm2, mm3;
    {
        const size_t st = (size_t)B_SZ * T_TAGS;
        mm0 = __ldg(&mask[0 * B_SZ + b]);  mm1 = __ldg(&mask[1 * B_SZ + b]);
        mm2 = __ldg(&mask[2 * B_SZ + b]);  mm3 = __ldg(&mask[3 * B_SZ + b]);
        fa0 = __ldg(&feats[0 * st + b * T_TAGS + j0]);  fb0 = __ldg(&feats[0 * st + b * T_TAGS + j1]);
        fa1 = __ldg(&feats[1 * st + b * T_TAGS + j0]);  fb1 = __ldg(&feats[1 * st + b * T_TAGS + j1]);
        fa2 = __ldg(&feats[2 * st + b * T_TAGS + j0]);  fb2 = __ldg(&feats[2 * st + b * T_TAGS + j1]);
        fa3 = __ldg(&feats[3 * st + b * T_TAGS + j0]);  fb3 = __ldg(&feats[3 * st + b * T_TAGS + j1]);
    }
    const float* fptr = feats + ((size_t)4 * B_SZ + b) * T_TAGS;  // base of step s+4
    const float* mptr = mask + 4 * B_SZ + b;

    // ---------------- forward recursion ----------------
    // invariant: true log_alpha[j] = log(A[j]) + C - 10000
    float C = 0.0f, lmx = 0.0f, rinv = 1.0f;
    float val0 = 0.0f, val1 = 0.0f;
    bool started = false;

#define STEP(K, MC, FA, FB)                                                    \
    do {                                                                       \
        float mc = (MC), f0v = (FA), f1v = (FB);                               \
        if (s + 4 + (K) < S_LEN) {                                             \
            (MC) = __ldg(mptr + (K) * B_SZ);                                   \
            (FA) = __ldg(fptr + (size_t)(K) * B_SZ * T_TAGS + j0);             \
            (FB) = __ldg(fptr + (size_t)(K) * B_SZ * T_TAGS + j1);             \
        }                                                                      \
        if (mc > 0.0f) {                                                       \
            if (started) {                                                     \
                const ulonglong2* AU = (const ulonglong2*)A[warp];             \
                u64 p0 = 0, p1 = 0, p2 = 0, p3 = 0;                            \
                u64 q0 = 0, q1 = 0, q2 = 0, q3 = 0;                            \
                _Pragma("unroll")                                              \
                for (int q = 0; q < 8; q++) {                                  \
                    ulonglong2 x = AU[2 * q];                                  \
                    ulonglong2 y = AU[2 * q + 1];                              \
                    p0 = fma2(x.x, E0p[4 * q + 0], p0);                        \
                    q0 = fma2(x.x, E1p[4 * q + 0], q0);                        \
                    p1 = fma2(x.y, E0p[4 * q + 1], p1);                        \
                    q1 = fma2(x.y, E1p[4 * q + 1], q1);                        \
                    p2 = fma2(y.x, E0p[4 * q + 2], p2);                        \
                    q2 = fma2(y.x, E1p[4 * q + 2], q2);                        \
                    p3 = fma2(y.y, E0p[4 * q + 3], p3);                        \
                    q3 = fma2(y.y, E1p[4 * q + 3], q3);                        \
                }                                                              \
                u64 ps = add2(add2(p0, p1), add2(p2, p3));                     \
                u64 qs = add2(add2(q0, q1), add2(q2, q3));                     \
                float x0, x1, y0, y1;                                          \
                upk2(ps, x0, x1); upk2(qs, y0, y1);                            \
                float ef0 = __expf(f0v), ef1 = __expf(f1v);                    \
                val0 = (x0 + x1) * ef0;                                        \
                val1 = (y0 + y1) * ef1;                                        \
                if ((K) == 3) { val0 *= rinv; val1 *= rinv; C += lmx; }        \
            } else {                                                           \
                val0 = __expf(f0v) * w0;                                       \
                val1 = __expf(f1v) * w1;                                       \
                started = true;                                                \
            }                                                                  \
            A[warp][j0] = val0;                                                \
            A[warp][j1] = val1;                                                \
            if ((K) == 2) {    /* lagged rescale: fully off the step chain */  \
                float v = fmaxf(val0, val1);                                   \
                _Pragma("unroll")                                              \
                for (int o = 16; o; o >>= 1)                                   \
                    v = fmaxf(v, __shfl_xor_sync(0xffffffffu, v, o));          \
                lmx  = __logf(v);                                              \
                rinv = __fdividef(1.0f, v);                                    \
            }                                                                  \
        }                                                                      \
        __syncwarp();                                                          \
    } while (0)

    for (int s = 0; s < S_LEN; s += 4) {
        STEP(0, mm0, fa0, fb0);
        STEP(1, mm1, fa1, fb1);
        STEP(2, mm2, fa2, fb2);
        STEP(3, mm3, fa3, fb3);
        fptr += (size_t)4 * B_SZ * T_TAGS;
        mptr += 4 * B_SZ;
    }
#undef STEP

    // ---------------- log_z and per-batch result ----------------
    float fv0 = started ? val0 : ((j0 == START_TAG) ? 1.0f : 0.0f);
    float fv1 = started ? val1 : ((j1 == START_TAG) ? 1.0f : 0.0f);
    if (!started) C = 10000.0f;
    float p = fv0 * Es0 + fv1 * Es1;
#pragma unroll
    for (int off = 16; off; off >>= 1)
        p += __shfl_xor_sync(0xffffffffu, p, off);
    if (lane == 0) {
        float logz = C + __logf(p) - 10000.0f;
        g_res[b] = logz - score_total;
        __threadfence();
    }

    // ---------------- fused finalize: last block reduces ----------------
    __syncthreads();
    if (threadIdx.x == 0) s_t = atomicInc(&g_ticket, GRID_X - 1);
    __syncthreads();
    if (s_t == GRID_X - 1) {
        __threadfence();
        const volatile float* gr = g_res;
        const int t = threadIdx.x;
        float v = gr[t] + gr[t + 128] + gr[t + 256] + gr[t + 384];
#pragma unroll
        for (int off = 16; off; off >>= 1)
            v += __shfl_xor_sync(0xffffffffu, v, off);
        if (lane == 0) sred[warp] = v;
        __syncthreads();
        if (t == 0)
            out[0] = (sred[0] + sred[1] + sred[2] + sred[3]) * (1.0f / (float)B_SZ);
    }
}

extern "C" void kernel_launch(void* const* d_in, const int* in_sizes, int n_in,
                              void* d_out, int out_size)
{
    const float* feats = (const float*)d_in[0];
    const int*   tags  = (const int*)d_in[1];
    const float* mask  = (const float*)d_in[2];
    const float* trans = (const float*)d_in[3];
    float* out = (float*)d_out;

    crf_forward_kernel<<<GRID_X, 128>>>(feats, tags, mask, trans, out);
}

// round 5
// speedup vs baseline: 3.4436x; 1.4970x over previous
#include <cuda_runtime.h>

#define S_LEN 512
#define B_SZ 512
#define T_TAGS 64
#define START_TAG 62
#define STOP_TAG 63
#define NWARP 4
#define GRID_X (B_SZ / NWARP)   // 128 blocks

__device__ float g_res[B_SZ];
__device__ unsigned g_ticket = 0;   // wraps every GRID_X -> graph-replay safe

typedef unsigned long long u64;

static __device__ __forceinline__ u64 pk2(float lo, float hi) {
    u64 r; asm("mov.b64 %0, {%1, %2};" : "=l"(r) : "f"(lo), "f"(hi)); return r;
}
static __device__ __forceinline__ void upk2(u64 v, float& lo, float& hi) {
    asm("mov.b64 {%0, %1}, %2;" : "=f"(lo), "=f"(hi) : "l"(v));
}
static __device__ __forceinline__ u64 fma2(u64 a, u64 b, u64 c) {
    u64 d; asm("fma.rn.f32x2 %0, %1, %2, %3;" : "=l"(d) : "l"(a), "l"(b), "l"(c)); return d;
}
static __device__ __forceinline__ u64 add2(u64 a, u64 b) {
    u64 d; asm("add.rn.f32x2 %0, %1, %2;" : "=l"(d) : "l"(a), "l"(b)); return d;
}

__global__ __launch_bounds__(128)
void crf_forward_kernel(const float* __restrict__ feats,
                        const int* __restrict__ tags,
                        const float* __restrict__ mask,
                        const float* __restrict__ trans,
                        float* __restrict__ out)
{
    const int warp = threadIdx.x >> 5;
    const int lane = threadIdx.x & 31;
    const int b    = blockIdx.x * NWARP + warp;     // one batch per warp
    const int j0   = lane, j1 = lane + 32;

    __shared__ __align__(16) float A[NWARP][T_TAGS];
    __shared__ float sred[NWARP];
    __shared__ unsigned s_t;
    float* const Aw = A[warp];

    // ---------------- gold score (per-warp, parallel over s) ----------------
    float sc = 0.0f, msum = 0.0f;
#pragma unroll 4
    for (int s = lane; s < S_LEN; s += 32) {
        int   tg = __ldg(&tags[s * B_SZ + b]);
        int   pv = (s == 0) ? START_TAG : __ldg(&tags[(s - 1) * B_SZ + b]);
        float m  = __ldg(&mask[s * B_SZ + b]);
        float e  = __ldg(&feats[((size_t)s * B_SZ + b) * T_TAGS + tg]);
        sc   += (e + __ldg(&trans[pv * T_TAGS + tg])) * m;
        msum += m;
    }
#pragma unroll
    for (int off = 16; off; off >>= 1) {
        sc   += __shfl_xor_sync(0xffffffffu, sc, off);
        msum += __shfl_xor_sync(0xffffffffu, msum, off);
    }
    float score_total = 0.0f;
    if (lane == 0) {
        int li = (int)(msum + 0.5f) - 1;
        int lt = __ldg(&tags[li * B_SZ + b]);
        score_total = sc + __ldg(&trans[lt * T_TAGS + STOP_TAG]);
    }

    // ---------------- E columns packed f32x2 ----------------
    u64 E0p[T_TAGS / 2], E1p[T_TAGS / 2];
    float w0 = 1.0f, w1 = 1.0f;                 // step-1 analytic weights
#pragma unroll
    for (int i = 0; i < T_TAGS / 2; i++) {
        float a0 = __expf(__ldg(&trans[(2 * i)     * T_TAGS + j0]));
        float a1 = __expf(__ldg(&trans[(2 * i + 1) * T_TAGS + j0]));
        float c0 = __expf(__ldg(&trans[(2 * i)     * T_TAGS + j1]));
        float c1 = __expf(__ldg(&trans[(2 * i + 1) * T_TAGS + j1]));
        E0p[i] = pk2(a0, a1);  w0 += a0 + a1;
        E1p[i] = pk2(c0, c1);  w1 += c0 + c1;
    }
    const float Es0 = __expf(__ldg(&trans[STOP_TAG * T_TAGS + j0]));
    const float Es1 = __expf(__ldg(&trans[STOP_TAG * T_TAGS + j1]));

    // ---------------- register prefetch for steps 0..3 ----------------
    const size_t st = (size_t)B_SZ * T_TAGS;
    float fa0, fa1, fa2, fa3, fb0, fb1, fb2, fb3, mm0, mm1, mm2, mm3;
    mm0 = __ldg(&mask[0 * B_SZ + b]);  mm1 = __ldg(&mask[1 * B_SZ + b]);
    mm2 = __ldg(&mask[2 * B_SZ + b]);  mm3 = __ldg(&mask[3 * B_SZ + b]);
    fa0 = __ldg(&feats[0 * st + b * T_TAGS + j0]);  fb0 = __ldg(&feats[0 * st + b * T_TAGS + j1]);
    fa1 = __ldg(&feats[1 * st + b * T_TAGS + j0]);  fb1 = __ldg(&feats[1 * st + b * T_TAGS + j1]);
    fa2 = __ldg(&feats[2 * st + b * T_TAGS + j0]);  fb2 = __ldg(&feats[2 * st + b * T_TAGS + j1]);
    fa3 = __ldg(&feats[3 * st + b * T_TAGS + j0]);  fb3 = __ldg(&feats[3 * st + b * T_TAGS + j1]);
    const float* fptr = feats + 4 * st + b * T_TAGS;   // base of step s+4
    const float* mptr = mask + 4 * B_SZ + b;

    // ---------------- forward recursion ----------------
    // invariant: true log_alpha[j] = log(A[j]) + C - 10000
    float C = 0.0f, lmx = 0.0f, rinv = 1.0f;
    float val0 = 0.0f, val1 = 0.0f;

    // FIRST: analytic start step (mask[0] > 0 for this dataset).
    // REFILL: loads for step s+4+K, known in-bounds in the main loop.
#define STEP(K, FIRST, REFILL, MC, FA, FB)                                     \
    do {                                                                       \
        float mc = (MC), f0v = (FA), f1v = (FB);                               \
        if (REFILL) {                                                          \
            (MC) = __ldg(mptr + (K) * B_SZ);                                   \
            (FA) = __ldg(fptr + (size_t)(K) * st + j0);                        \
            (FB) = __ldg(fptr + (size_t)(K) * st + j1);                        \
        }                                                                      \
        float nv0, nv1;                                                        \
        if (FIRST) {                                                           \
            nv0 = __expf(f0v) * w0;                                            \
            nv1 = __expf(f1v) * w1;                                            \
        } else {                                                               \
            float ef0 = __expf(f0v), ef1 = __expf(f1v);                        \
            const ulonglong2* AU = (const ulonglong2*)Aw;                      \
            u64 p0 = 0, p1 = 0, p2 = 0, p3 = 0;                                \
            u64 q0 = 0, q1 = 0, q2 = 0, q3 = 0;                                \
            _Pragma("unroll")                                                  \
            for (int q = 0; q < 8; q++) {                                      \
                ulonglong2 x = AU[2 * q];                                      \
                ulonglong2 y = AU[2 * q + 1];                                  \
                p0 = fma2(x.x, E0p[4 * q + 0], p0);                            \
                q0 = fma2(x.x, E1p[4 * q + 0], q0);                            \
                p1 = fma2(x.y, E0p[4 * q + 1], p1);                            \
                q1 = fma2(x.y, E1p[4 * q + 1], q1);                            \
                p2 = fma2(y.x, E0p[4 * q + 2], p2);                            \
                q2 = fma2(y.x, E1p[4 * q + 2], q2);                            \
                p3 = fma2(y.y, E0p[4 * q + 3], p3);                            \
                q3 = fma2(y.y, E1p[4 * q + 3], q3);                            \
            }                                                                  \
            u64 ps = add2(add2(p0, p1), add2(p2, p3));                         \
            u64 qs = add2(add2(q0, q1), add2(q2, q3));                         \
            float x0, x1, y0, y1;                                              \
            upk2(ps, x0, x1); upk2(qs, y0, y1);                                \
            nv0 = (x0 + x1) * ef0;                                             \
            nv1 = (y0 + y1) * ef1;                                             \
            if ((K) == 3) { nv0 *= rinv; nv1 *= rinv; }                        \
        }                                                                      \
        val0 = (mc > 0.0f) ? nv0 : val0;  /* FSEL, no branch */                \
        val1 = (mc > 0.0f) ? nv1 : val1;                                       \
        if ((K) == 3) C += lmx;                                                \
        Aw[j0] = val0;                                                         \
        Aw[j1] = val1;                                                         \
        if ((K) == 2) {   /* lagged rescale, single REDUX (positive floats) */ \
            float v = fmaxf(val0, val1);                                       \
            v = __uint_as_float(                                               \
                __reduce_max_sync(0xffffffffu, __float_as_uint(v)));           \
            lmx  = __logf(v);                                                  \
            rinv = __fdividef(1.0f, v);                                        \
        }                                                                      \
        __syncwarp();                                                          \
    } while (0)

    // peeled first group: steps 0..3, refills steps 4..7
    STEP(0, 1, 1, mm0, fa0, fb0);
    STEP(1, 0, 1, mm1, fa1, fb1);
    STEP(2, 0, 1, mm2, fa2, fb2);
    STEP(3, 0, 1, mm3, fa3, fb3);
    fptr += 4 * st;  mptr += 4 * B_SZ;

    // steady state: branchless body, unconditional in-bounds refills
    for (int s = 4; s <= 504; s += 4) {
        STEP(0, 0, 1, mm0, fa0, fb0);
        STEP(1, 0, 1, mm1, fa1, fb1);
        STEP(2, 0, 1, mm2, fa2, fb2);
        STEP(3, 0, 1, mm3, fa3, fb3);
        fptr += 4 * st;  mptr += 4 * B_SZ;
    }

    // epilogue group: steps 508..511, no refill
    STEP(0, 0, 0, mm0, fa0, fb0);
    STEP(1, 0, 0, mm1, fa1, fb1);
    STEP(2, 0, 0, mm2, fa2, fb2);
    STEP(3, 0, 0, mm3, fa3, fb3);
#undef STEP

    // ---------------- log_z and per-batch result ----------------
    float p = val0 * Es0 + val1 * Es1;
#pragma unroll
    for (int off = 16; off; off >>= 1)
        p += __shfl_xor_sync(0xffffffffu, p, off);
    if (lane == 0) {
        float logz = C + __logf(p) - 10000.0f;
        g_res[b] = logz - score_total;
        __threadfence();
    }

    // ---------------- fused finalize: last block reduces ----------------
    __syncthreads();
    if (threadIdx.x == 0) s_t = atomicInc(&g_ticket, GRID_X - 1);
    __syncthreads();
    if (s_t == GRID_X - 1) {
        __threadfence();
        const volatile float* gr = g_res;
        const int t = threadIdx.x;
        float v = gr[t] + gr[t + 128] + gr[t + 256] + gr[t + 384];
#pragma unroll
        for (int off = 16; off; off >>= 1)
            v += __shfl_xor_sync(0xffffffffu, v, off);
        if (lane == 0) sred[warp] = v;
        __syncthreads();
        if (t == 0)
            out[0] = (sred[0] + sred[1] + sred[2] + sred[3]) * (1.0f / (float)B_SZ);
    }
}

extern "C" void kernel_launch(void* const* d_in, const int* in_sizes, int n_in,
                              void* d_out, int out_size)
{
    const float* feats = (const float*)d_in[0];
    const int*   tags  = (const int*)d_in[1];
    const float* mask  = (const float*)d_in[2];
    const float* trans = (const float*)d_in[3];
    float* out = (float*)d_out;

    crf_forward_kernel<<<GRID_X, 128>>>(feats, tags, mask, trans, out);
}